// round 1
// baseline (speedup 1.0000x reference)
#include <cuda_runtime.h>
#include <math.h>

#define NB 8
#define NC 256
#define NP1 1024      // 32*32
#define NP2 256       // 16*16
#define NINNER 512
#define NHEADS 8
#define NDH 64
#define ATT_SCALE 0.125f
#define BN_EPS 1e-5f

// ---------------- scratch (global memory via __device__ arrays) ----------------
__device__ float g_hq [2][NB][NC][NP1];        // dw+bn (stride 1) output
__device__ float g_hkv[2][NB][NC][NP2];        // dw+bn (stride 2) output
__device__ float g_q  [2][NB][NINNER][NP1];    // q projection
__device__ float g_kv [2][NB][2*NINNER][NP2];  // k|v projection
__device__ float g_ao [2][NB][NINNER][NP1];    // attention output

// ---------------- depthwise conv (stride 1) + BN ----------------
__global__ __launch_bounds__(1024)
void dwbn1_kernel(const float* __restrict__ x0, const float* __restrict__ x1,
                  const float* __restrict__ wdw,
                  const float* __restrict__ gamma, const float* __restrict__ beta,
                  const float* __restrict__ mean,  const float* __restrict__ var)
{
    int inp = blockIdx.y;
    int bc  = blockIdx.x;           // b*256 + c
    int c   = bc & 255;
    int b   = bc >> 8;
    const float* in = (inp ? x1 : x0) + (size_t)bc * 1024;

    __shared__ float t[34][34];
    int tid = threadIdx.x;
    for (int i = tid; i < 34 * 34; i += 1024) {
        int r = i / 34 - 1, q = i % 34 - 1;
        t[i / 34][i % 34] = (r >= 0 && r < 32 && q >= 0 && q < 32) ? in[r * 32 + q] : 0.f;
    }
    float w0 = wdw[c*9+0], w1 = wdw[c*9+1], w2 = wdw[c*9+2];
    float w3 = wdw[c*9+3], w4 = wdw[c*9+4], w5 = wdw[c*9+5];
    float w6 = wdw[c*9+6], w7 = wdw[c*9+7], w8 = wdw[c*9+8];
    __syncthreads();

    int ty = tid >> 5, tx = tid & 31;
    float acc = t[ty  ][tx] * w0 + t[ty  ][tx+1] * w1 + t[ty  ][tx+2] * w2
              + t[ty+1][tx] * w3 + t[ty+1][tx+1] * w4 + t[ty+1][tx+2] * w5
              + t[ty+2][tx] * w6 + t[ty+2][tx+1] * w7 + t[ty+2][tx+2] * w8;
    float s = gamma[c] * rsqrtf(var[c] + BN_EPS);
    g_hq[inp][b][c][tid] = (acc - mean[c]) * s + beta[c];
}

// ---------------- depthwise conv (stride 2) + BN ----------------
__global__ __launch_bounds__(256)
void dwbn2_kernel(const float* __restrict__ x0, const float* __restrict__ x1,
                  const float* __restrict__ wdw,
                  const float* __restrict__ gamma, const float* __restrict__ beta,
                  const float* __restrict__ mean,  const float* __restrict__ var)
{
    int inp = blockIdx.y;
    int bc  = blockIdx.x;
    int c   = bc & 255;
    int b   = bc >> 8;
    const float* in = (inp ? x1 : x0) + (size_t)bc * 1024;

    __shared__ float t[32][32];
    int tid = threadIdx.x;
    for (int i = tid; i < 1024; i += 256) t[i / 32][i % 32] = in[i];

    float w[9];
#pragma unroll
    for (int i = 0; i < 9; i++) w[i] = wdw[c * 9 + i];
    __syncthreads();

    int oy = tid >> 4, ox = tid & 15;
    int iy = oy * 2 - 1, ix = ox * 2 - 1;
    float acc = 0.f;
#pragma unroll
    for (int kh = 0; kh < 3; kh++) {
#pragma unroll
        for (int kw = 0; kw < 3; kw++) {
            int r = iy + kh, q = ix + kw;
            if (r >= 0 && r < 32 && q >= 0 && q < 32) acc += t[r][q] * w[kh * 3 + kw];
        }
    }
    float s = gamma[c] * rsqrtf(var[c] + BN_EPS);
    g_hkv[inp][b][c][tid] = (acc - mean[c]) * s + beta[c];
}

// ---------------- batched SGEMM: C[b] = A[M,K] @ X[b][K,P] (+bias) ----------------
// BM=BN=128, BK=16, 256 threads, 8x8 microtile
__global__ __launch_bounds__(256)
void sgemm_kernel(const float* __restrict__ A, const float* __restrict__ Xbase,
                  float* __restrict__ Cbase, int M, int K, int P,
                  const float* __restrict__ bias)
{
    const float* X = Xbase + (size_t)blockIdx.z * K * P;
    float*       Cp = Cbase + (size_t)blockIdx.z * M * P;

    __shared__ float As[16][132];
    __shared__ float Bs[16][128];

    int tid = threadIdx.x;
    int tx = tid & 15, ty = tid >> 4;
    int m0 = blockIdx.y * 128, n0 = blockIdx.x * 128;

    float acc[8][8];
#pragma unroll
    for (int i = 0; i < 8; i++)
#pragma unroll
        for (int j = 0; j < 8; j++) acc[i][j] = 0.f;

    for (int k0 = 0; k0 < K; k0 += 16) {
#pragma unroll
        for (int u = 0; u < 2; u++) {
            int idx = tid * 2 + u;               // 0..511 float4 units
            int row = idx >> 2;                  // 0..127
            int fid = idx & 3;
            float4 v = *(const float4*)&A[(size_t)(m0 + row) * K + k0 + fid * 4];
            As[fid * 4 + 0][row] = v.x;
            As[fid * 4 + 1][row] = v.y;
            As[fid * 4 + 2][row] = v.z;
            As[fid * 4 + 3][row] = v.w;
        }
#pragma unroll
        for (int u = 0; u < 2; u++) {
            int idx = tid * 2 + u;
            int row = idx >> 5;                  // 0..15
            int col = (idx & 31) * 4;
            *(float4*)&Bs[row][col] = *(const float4*)&X[(size_t)(k0 + row) * P + n0 + col];
        }
        __syncthreads();

#pragma unroll
        for (int k = 0; k < 16; k++) {
            float a[8], bb[8];
            *(float4*)&a[0]  = *(const float4*)&As[k][ty * 8];
            *(float4*)&a[4]  = *(const float4*)&As[k][ty * 8 + 4];
            *(float4*)&bb[0] = *(const float4*)&Bs[k][tx * 8];
            *(float4*)&bb[4] = *(const float4*)&Bs[k][tx * 8 + 4];
#pragma unroll
            for (int i = 0; i < 8; i++)
#pragma unroll
                for (int j = 0; j < 8; j++) acc[i][j] += a[i] * bb[j];
        }
        __syncthreads();
    }

#pragma unroll
    for (int i = 0; i < 8; i++) {
        int m = m0 + ty * 8 + i;
        float bv = bias ? bias[m] : 0.f;
        float4 o0 = make_float4(acc[i][0] + bv, acc[i][1] + bv, acc[i][2] + bv, acc[i][3] + bv);
        float4 o1 = make_float4(acc[i][4] + bv, acc[i][5] + bv, acc[i][6] + bv, acc[i][7] + bv);
        *(float4*)&Cp[(size_t)m * P + n0 + tx * 8]     = o0;
        *(float4*)&Cp[(size_t)m * P + n0 + tx * 8 + 4] = o1;
    }
}

// ---------------- fused attention ----------------
// grid: (16 i-tiles, B*HEADS, 2 dirs), 256 threads
// dir 0: outx = attn(qx, ky, vy);  dir 1: outy = attn(qy, kx, vx)
#define SM_Q  0
#define SM_K  (64 * 64)
#define SM_S  (64 * 64 + 64 * 256)
#define S_LD  260
#define ATTN_SMEM ((64 * 64 + 64 * 256 + 64 * S_LD) * 4)

__global__ __launch_bounds__(256)
void attn_kernel()
{
    extern __shared__ float sm[];
    float* qs = sm + SM_Q;   // [64 d][64 i]
    float* ks = sm + SM_K;   // [64 d][256 j]   (reused for V in phase 2)
    float* S  = sm + SM_S;   // [64 i][260]

    int dir = blockIdx.z;
    int bh  = blockIdx.y;
    int b   = bh >> 3, h = bh & 7;
    int i0  = blockIdx.x * 64;
    int qin = dir, kin = dir ^ 1;
    int tid = threadIdx.x;

    // load Q tile: qs[d][i] = g_q[qin][b][h*64+d][i0+i]
#pragma unroll
    for (int u = 0; u < 4; u++) {
        int idx = tid + u * 256;          // float4 units, 0..1023
        int d  = idx >> 4;
        int i4 = (idx & 15) * 4;
        *(float4*)&qs[d * 64 + i4] = *(const float4*)&g_q[qin][b][h * 64 + d][i0 + i4];
    }
    // load K: ks[d][j]
#pragma unroll
    for (int u = 0; u < 16; u++) {
        int idx = tid + u * 256;          // 0..4095 float4 units
        int d  = idx >> 6;
        int j4 = (idx & 63) * 4;
        *(float4*)&ks[d * 256 + j4] = *(const float4*)&g_kv[kin][b][h * 64 + d][j4];
    }
    __syncthreads();

    // phase 1: S[i][j] = SCALE * sum_d qs[d][i]*ks[d][j]
    {
        int ti = tid & 7, tj = tid >> 3;
        int ib = ti * 8, jb = tj * 8;
        float acc[8][8];
#pragma unroll
        for (int i = 0; i < 8; i++)
#pragma unroll
            for (int j = 0; j < 8; j++) acc[i][j] = 0.f;

#pragma unroll 4
        for (int d = 0; d < 64; d++) {
            float a[8], bb[8];
            *(float4*)&a[0]  = *(const float4*)&qs[d * 64 + ib];
            *(float4*)&a[4]  = *(const float4*)&qs[d * 64 + ib + 4];
            *(float4*)&bb[0] = *(const float4*)&ks[d * 256 + jb];
            *(float4*)&bb[4] = *(const float4*)&ks[d * 256 + jb + 4];
#pragma unroll
            for (int i = 0; i < 8; i++)
#pragma unroll
                for (int j = 0; j < 8; j++) acc[i][j] += a[i] * bb[j];
        }
#pragma unroll
        for (int i = 0; i < 8; i++) {
            float4 s0 = make_float4(acc[i][0] * ATT_SCALE, acc[i][1] * ATT_SCALE,
                                    acc[i][2] * ATT_SCALE, acc[i][3] * ATT_SCALE);
            float4 s1 = make_float4(acc[i][4] * ATT_SCALE, acc[i][5] * ATT_SCALE,
                                    acc[i][6] * ATT_SCALE, acc[i][7] * ATT_SCALE);
            *(float4*)&S[(ib + i) * S_LD + jb]     = s0;
            *(float4*)&S[(ib + i) * S_LD + jb + 4] = s1;
        }
    }
    __syncthreads();

    // load V into ks (overwrite), overlapping with softmax below
#pragma unroll
    for (int u = 0; u < 16; u++) {
        int idx = tid + u * 256;
        int d  = idx >> 6;
        int j4 = (idx & 63) * 4;
        *(float4*)&ks[d * 256 + j4] = *(const float4*)&g_kv[kin][b][NINNER + h * 64 + d][j4];
    }

    // softmax over j (256) per row, 8 warps x 8 rows
    {
        int warp = tid >> 5, lane = tid & 31;
#pragma unroll
        for (int r = 0; r < 8; r++) {
            int i = warp * 8 + r;
            float vals[8];
            float vmax = -1e30f;
#pragma unroll
            for (int u = 0; u < 8; u++) {
                vals[u] = S[i * S_LD + lane + u * 32];
                vmax = fmaxf(vmax, vals[u]);
            }
#pragma unroll
            for (int off = 16; off > 0; off >>= 1)
                vmax = fmaxf(vmax, __shfl_xor_sync(0xffffffffu, vmax, off));
            float sum = 0.f;
#pragma unroll
            for (int u = 0; u < 8; u++) { vals[u] = __expf(vals[u] - vmax); sum += vals[u]; }
#pragma unroll
            for (int off = 16; off > 0; off >>= 1)
                sum += __shfl_xor_sync(0xffffffffu, sum, off);
            float inv = 1.f / sum;
#pragma unroll
            for (int u = 0; u < 8; u++) S[i * S_LD + lane + u * 32] = vals[u] * inv;
        }
    }
    __syncthreads();

    // phase 2: out[d][i] = sum_j S[i][j] * V[d][j]
    {
        int txq = tid & 15, tyq = tid >> 4;
        int ib2 = txq * 4, db = tyq * 4;
        float acc2[4][4];
#pragma unroll
        for (int d = 0; d < 4; d++)
#pragma unroll
            for (int i = 0; i < 4; i++) acc2[d][i] = 0.f;

        for (int j = 0; j < 256; j += 4) {
            float4 vv[4], ss[4];
#pragma unroll
            for (int d = 0; d < 4; d++) vv[d] = *(const float4*)&ks[(db + d) * 256 + j];
#pragma unroll
            for (int i = 0; i < 4; i++) ss[i] = *(const float4*)&S[(ib2 + i) * S_LD + j];
#pragma unroll
            for (int d = 0; d < 4; d++)
#pragma unroll
                for (int i = 0; i < 4; i++)
                    acc2[d][i] += vv[d].x * ss[i].x + vv[d].y * ss[i].y
                                + vv[d].z * ss[i].z + vv[d].w * ss[i].w;
        }
#pragma unroll
        for (int d = 0; d < 4; d++) {
            float4 o = make_float4(acc2[d][0], acc2[d][1], acc2[d][2], acc2[d][3]);
            *(float4*)&g_ao[qin][b][h * 64 + db + d][i0 + ib2] = o;
        }
    }
}

// ---------------- launch ----------------
extern "C" void kernel_launch(void* const* d_in, const int* in_sizes, int n_in,
                              void* d_out, int out_size)
{
    const float* x      = (const float*)d_in[0];
    const float* y      = (const float*)d_in[1];
    const float* q_dw_w = (const float*)d_in[2];
    const float* q_g    = (const float*)d_in[3];
    const float* q_b    = (const float*)d_in[4];
    const float* q_m    = (const float*)d_in[5];
    const float* q_v    = (const float*)d_in[6];
    const float* q_pw   = (const float*)d_in[7];
    const float* kv_dw_w= (const float*)d_in[8];
    const float* kv_g   = (const float*)d_in[9];
    const float* kv_b   = (const float*)d_in[10];
    const float* kv_m   = (const float*)d_in[11];
    const float* kv_v   = (const float*)d_in[12];
    const float* kv_pw  = (const float*)d_in[13];
    const float* out_w  = (const float*)d_in[14];
    const float* out_b  = (const float*)d_in[15];
    float* out = (float*)d_out;

    float *p_hq, *p_hkv, *p_q, *p_kv, *p_ao;
    cudaGetSymbolAddress((void**)&p_hq,  g_hq);
    cudaGetSymbolAddress((void**)&p_hkv, g_hkv);
    cudaGetSymbolAddress((void**)&p_q,   g_q);
    cudaGetSymbolAddress((void**)&p_kv,  g_kv);
    cudaGetSymbolAddress((void**)&p_ao,  g_ao);

    // stage 1: depthwise conv + BN (both inputs)
    dwbn1_kernel<<<dim3(NB * NC, 2), 1024>>>(x, y, q_dw_w, q_g, q_b, q_m, q_v);
    dwbn2_kernel<<<dim3(NB * NC, 2), 256>>>(x, y, kv_dw_w, kv_g, kv_b, kv_m, kv_v);

    // stage 2: pointwise projections
    for (int inp = 0; inp < 2; inp++) {
        sgemm_kernel<<<dim3(NP1 / 128, NINNER / 128, NB), 256>>>(
            q_pw,
            p_hq + (size_t)inp * NB * NC * NP1,
            p_q  + (size_t)inp * NB * NINNER * NP1,
            NINNER, NC, NP1, nullptr);
        sgemm_kernel<<<dim3(NP2 / 128, (2 * NINNER) / 128, NB), 256>>>(
            kv_pw,
            p_hkv + (size_t)inp * NB * NC * NP2,
            p_kv  + (size_t)inp * NB * 2 * NINNER * NP2,
            2 * NINNER, NC, NP2, nullptr);
    }

    // stage 3: fused cross-attention, both directions
    cudaFuncSetAttribute(attn_kernel, cudaFuncAttributeMaxDynamicSharedMemorySize, ATTN_SMEM);
    attn_kernel<<<dim3(NP1 / 64, NB * NHEADS, 2), 256, ATTN_SMEM>>>();

    // stage 4: output projection (+bias) straight into d_out; tuple is (outx, outy)
    for (int inp = 0; inp < 2; inp++) {
        sgemm_kernel<<<dim3(NP1 / 128, NC / 128, NB), 256>>>(
            out_w,
            p_ao + (size_t)inp * NB * NINNER * NP1,
            out  + (size_t)inp * NB * NC * NP1,
            NC, NINNER, NP1, out_b);
    }
}